// round 9
// baseline (speedup 1.0000x reference)
#include <cuda_runtime.h>
#include <math.h>

// LundWeight reweighting, round 9: NO compaction. Math fused directly into the
// load loop over the valid region, fully predicated (masked lanes compute on
// z=0.5 and contribute weight 1, matching the reference's where(mask,w,1)).
// Removes: compaction scan, shared z-buffer, atomics, one __syncthreads.
// z (8192,128,25) f32; mT (8192,128) f32; observable (8192,2) i32 (mult=[:,0]).
// Output (8192,) f32.

#define LOG2E 1.4426950408889634f
#define F2MIN (-72.13475f)  /* -50 * LOG2E */
#define OSF   15.0f

__device__ __forceinline__ float rcp_fast(float x){ float r; asm("rcp.approx.f32 %0,%1;":"=f"(r):"f"(x)); return r; }
__device__ __forceinline__ float lg2_fast(float x){ float r; asm("lg2.approx.f32 %0,%1;":"=f"(r):"f"(x)); return r; }
__device__ __forceinline__ float ex2_fast(float x){ float r; asm("ex2.approx.f32 %0,%1;":"=f"(r):"f"(x)); return r; }

__device__ __forceinline__ float zmax_calc(float a, float b) {
    const float c = 1.0f;
    if (a < 0.02f) return (c > b) ? b : 1.0f;
    if (fabsf(a - c) < 0.01f) return b / (b + c);
    float z = 0.5f * (b + c - sqrtf((b - c) * (b - c) + 4.0f * a * b)) / (c - a);
    if (z > 0.9999f && b > 100.0f) z = fminf(z, 1.0f - a / b);
    return z;
}

__global__ __launch_bounds__(256) void lund_weight_kernel(
    const float4* __restrict__ Z4,     // (B,800) float4 view of (B,128,25)
    const float*  __restrict__ MT,     // (B,128)
    const int*    __restrict__ OBS,    // (B,2) int32, [:,0] = mult
    const float*  __restrict__ p_a,
    const float*  __restrict__ p_b,
    const float*  __restrict__ p_base,
    float* __restrict__ out)           // (B,)
{
    __shared__ float4 sK[128];      // {be2P, C2P, be20, C20} per m (log2 domain)
    __shared__ float  sRed[8];

    const int b    = blockIdx.x;
    const int tid  = threadIdx.x;
    const int lane = tid & 31;

    const float aP = p_a[0],    bP = p_b[0];
    const float a0 = p_base[0], b0 = p_base[1];
    const float aUP = (aP < 0.02f) ? 0.0f : aP;
    const float aU0 = (a0 < 0.02f) ? 0.0f : a0;

    const int mult = OBS[b * 2];             // 20..128

    // ---- Phase 1: 2 param-sets x 128 m; log2-domain constants:
    //      f2 = C2 - be2/z - lg2 z + aU*lg2(1-z);  be2 = b_exp*LOG2E;
    //      C2 = be2/zmax + lg2 zmax - aU*lg2(1-zmax).
    {
        const int   set  = tid >> 7;
        const int   m    = tid & 127;
        const float a    = set ? a0  : aP;
        const float bpar = set ? b0  : bP;
        const float aU   = set ? aU0 : aUP;
        const float mt   = MT[b * 128 + m];
        const float be   = bpar * mt * mt;
        const float zm   = zmax_calc(a, be);
        const float be2  = be * LOG2E;
        float C2 = be2 * rcp_fast(zm) + lg2_fast(zm);
        if (aU != 0.0f) C2 -= aU * lg2_fast(1.0f - zm);
        float* sKf = (float*)sK;
        sKf[(m << 2) + (set << 1) + 0] = be2;
        sKf[(m << 2) + (set << 1) + 1] = C2;
    }
    __syncthreads();

    // ---- Phase 2: fused load + predicated math over the valid region only
    //      (first mult*25 floats; the rest of the row is exactly zero). ----
    const float4* __restrict__ zr = Z4 + (size_t)b * 800;
    const int nq = (mult * 25 + 3) >> 2;     // quads covering valid region (<= 800)

    float prod = 1.0f;
    #pragma unroll 1
    for (int q = tid; q < nq; q += 256) {
        const float4 v    = zr[q];
        const int    idx0 = q << 2;
        const float  e[4] = {v.x, v.y, v.z, v.w};
        #pragma unroll
        for (int j = 0; j < 4; ++j) {
            const float zraw = e[j];
            const bool  act  = (zraw != 0.0f);
            const float z    = act ? zraw : 0.5f;        // benign placeholder
            const int   idx  = idx0 + j;
            const int   m    = (idx * 5243) >> 17;       // exact idx/25, idx<3200
            const bool  rej  = (idx - m * 25) != 0;
            const float4 kk  = sK[m];

            const float rz  = rcp_fast(z);
            const float l2z = lg2_fast(z);
            const float l2o = lg2_fast(1.0f - z);

            float fP = fmaf(-kk.x, rz, kk.y);
            fP = fmaf(aUP, l2o, fP - l2z);
            float f0 = fmaf(-kk.z, rz, kk.w);
            f0 = fmaf(aU0, l2o, f0 - l2z);
            fP = fmaxf(fP, F2MIN);            // f <= 0 by construction; lower clip only
            f0 = fmaxf(f0, F2MIN);
            const float eP = ex2_fast(fP);
            const float e0 = ex2_fast(f0);

            const float num = rej ? (OSF - eP) : eP;
            const float den = rej ? (OSF - e0) : e0;
            const float w   = num * rcp_fast(den);
            prod *= act ? w : 1.0f;
        }
    }

    // ---- Phase 3: block product reduction ----
    #pragma unroll
    for (int off = 16; off; off >>= 1)
        prod *= __shfl_xor_sync(0xffffffffu, prod, off);
    if (lane == 0) sRed[tid >> 5] = prod;
    __syncthreads();
    if (tid < 32) {
        float pr = (tid < 8) ? sRed[tid] : 1.0f;
        #pragma unroll
        for (int off = 4; off; off >>= 1)
            pr *= __shfl_xor_sync(0xffffffffu, pr, off);
        if (tid == 0) out[b] = pr;
    }
}

extern "C" void kernel_launch(void* const* d_in, const int* in_sizes, int n_in,
                              void* d_out, int out_size) {
    const float4* Z4     = (const float4*)d_in[0];
    const float*  MT     = (const float*)d_in[1];
    const int*    OBS    = (const int*)d_in[2];   // int32 on device
    const float*  p_a    = (const float*)d_in[3];
    const float*  p_b    = (const float*)d_in[4];
    const float*  p_base = (const float*)d_in[5];
    float* out = (float*)d_out;

    const int B = out_size;   // 8192
    lund_weight_kernel<<<B, 256>>>(Z4, MT, OBS, p_a, p_b, p_base, out);
}

// round 10
// speedup vs baseline: 1.0539x; 1.0539x over previous
#include <cuda_runtime.h>
#include <math.h>

// LundWeight reweighting, round 10: warp-local compaction pipeline.
//  - each warp scans its own interleaved quad set (coalesced), compacts into
//    its private smem segment via ONE warp prefix-sum (no atomics at all),
//    and runs dense math on its own segment with NO block sync in between.
//  - per-warp uniform skip of scan iterations beyond the valid region.
// z (8192,128,25) f32; mT (8192,128) f32; observable (8192,2) i32 (mult=[:,0]).
// Output (8192,) f32.

#define LOG2E 1.4426950408889634f
#define F2MIN (-72.13475f)  /* -50 * LOG2E */
#define OSF   15.0f

__device__ __forceinline__ float rcp_fast(float x){ float r; asm("rcp.approx.f32 %0,%1;":"=f"(r):"f"(x)); return r; }
__device__ __forceinline__ float lg2_fast(float x){ float r; asm("lg2.approx.f32 %0,%1;":"=f"(r):"f"(x)); return r; }
__device__ __forceinline__ float ex2_fast(float x){ float r; asm("ex2.approx.f32 %0,%1;":"=f"(r):"f"(x)); return r; }

__device__ __forceinline__ float zmax_calc(float a, float b) {
    const float c = 1.0f;
    if (a < 0.02f) return (c > b) ? b : 1.0f;
    if (fabsf(a - c) < 0.01f) return b / (b + c);
    float z = 0.5f * (b + c - sqrtf((b - c) * (b - c) + 4.0f * a * b)) / (c - a);
    if (z > 0.9999f && b > 100.0f) z = fminf(z, 1.0f - a / b);
    return z;
}

// Predicated shared store of {z, idx}: no branch, no wavefront when z == 0.
__device__ __forceinline__ void sts_pred(unsigned addr, float z, int idx) {
    asm volatile(
        "{ .reg .pred p; setp.ne.f32 p, %1, 0F00000000;\n\t"
        "  @p st.shared.v2.f32 [%0], {%1, %2}; }\n"
        :: "r"(addr), "f"(z), "f"(__int_as_float(idx)) : "memory");
}

__global__ __launch_bounds__(256) void lund_weight_kernel(
    const float4* __restrict__ Z4,     // (B,800) float4 view of (B,128,25)
    const float*  __restrict__ MT,     // (B,128)
    const int*    __restrict__ OBS,    // (B,2) int32, [:,0] = mult
    const float*  __restrict__ p_a,
    const float*  __restrict__ p_b,
    const float*  __restrict__ p_base,
    float* __restrict__ out)           // (B,)
{
    __shared__ float4 sK[128];          // {be2P, C2P, be20, C20} per m
    __shared__ float2 sSeg[8][512];     // per-warp compacted {z, idx}; cap 512 = hard max
    __shared__ float  sRed[8];

    const int b    = blockIdx.x;
    const int tid  = threadIdx.x;
    const int w    = tid >> 5;
    const int lane = tid & 31;

    const float aP = p_a[0],    bP = p_b[0];
    const float a0 = p_base[0], b0 = p_base[1];
    const float aUP = (aP < 0.02f) ? 0.0f : aP;
    const float aU0 = (a0 < 0.02f) ? 0.0f : a0;

    const int mult = OBS[b * 2];             // 20..128

    // ---- Phase 1: 2 param-sets x 128 m; log2-domain constants:
    //      f2 = C2 - be2/z - lg2 z + aU*lg2(1-z);  be2 = b_exp*LOG2E;
    //      C2 = be2/zmax + lg2 zmax - aU*lg2(1-zmax).
    {
        const int   set  = tid >> 7;
        const int   m    = tid & 127;
        const float a    = set ? a0  : aP;
        const float bpar = set ? b0  : bP;
        const float aU   = set ? aU0 : aUP;
        const float mt   = MT[b * 128 + m];
        const float be   = bpar * mt * mt;
        const float zm   = zmax_calc(a, be);
        const float be2  = be * LOG2E;
        float C2 = be2 * rcp_fast(zm) + lg2_fast(zm);
        if (aU != 0.0f) C2 -= aU * lg2_fast(1.0f - zm);
        float* sKf = (float*)sK;
        sKf[(m << 2) + (set << 1) + 0] = be2;
        sKf[(m << 2) + (set << 1) + 1] = C2;
    }
    __syncthreads();   // sK ready for all warps

    // ---- Phase 2: warp-local scan + compaction (no atomics, no block sync).
    //      Lane l of warp w reads quads g = k*256 + w*32 + l, k=0..3 — coalesced,
    //      covers [0,1024) ⊇ valid region [0,nq). Rows are zero beyond mult*25,
    //      so quad-granularity over-read inside [0,nq) is inert. ----
    const float4* __restrict__ zr = Z4 + (size_t)b * 800;
    const int nq = (mult * 25 + 3) >> 2;      // quads in valid region (<= 800)

    float4 q[4];
    int    g4[4];
    int c = 0;
    #pragma unroll
    for (int k = 0; k < 4; ++k) {
        const int g = (k << 8) + (w << 5) + lane;
        g4[k] = g << 2;
        q[k] = make_float4(0.f, 0.f, 0.f, 0.f);
        if (g < nq) q[k] = zr[g];             // warp-coherent predicate mostly
        c += (q[k].x != 0.f) + (q[k].y != 0.f) + (q[k].z != 0.f) + (q[k].w != 0.f);
    }

    // single warp-inclusive prefix sum over per-lane counts
    int inc = c;
    #pragma unroll
    for (int off = 1; off < 32; off <<= 1) {
        int t = __shfl_up_sync(0xffffffffu, inc, off);
        if (lane >= off) inc += t;
    }
    const int cnt = __shfl_sync(0xffffffffu, inc, 31);   // warp total
    int pos = inc - c;                                    // exclusive offset

    const unsigned segb = (unsigned)__cvta_generic_to_shared(&sSeg[w][0]);
    #pragma unroll
    for (int k = 0; k < 4; ++k) {
        const float e[4] = {q[k].x, q[k].y, q[k].z, q[k].w};
        #pragma unroll
        for (int j = 0; j < 4; ++j) {
            sts_pred(segb + (unsigned)pos * 8u, e[j], g4[k] + j);
            pos += (e[j] != 0.f);
        }
    }
    __syncwarp();

    // ---- Phase 3: dense math over this warp's own segment ----
    float prod = 1.0f;
    #pragma unroll 1
    for (int i = lane; i < cnt; i += 32) {
        const float2 p   = sSeg[w][i];
        const int    idx = __float_as_int(p.y);
        const int    m   = (idx * 5243) >> 17;   // exact idx/25 for idx<3200
        const bool   rej = (idx - m * 25) != 0;
        const float4 kk  = sK[m];
        const float  z   = p.x;

        const float rz  = rcp_fast(z);
        const float l2z = lg2_fast(z);
        const float l2o = lg2_fast(1.0f - z);

        float fP = fmaf(-kk.x, rz, kk.y);
        fP = fmaf(aUP, l2o, fP - l2z);
        float f0 = fmaf(-kk.z, rz, kk.w);
        f0 = fmaf(aU0, l2o, f0 - l2z);
        fP = fmaxf(fP, F2MIN);                // f <= 0 by construction
        f0 = fmaxf(f0, F2MIN);
        const float eP = ex2_fast(fP);
        const float e0 = ex2_fast(f0);

        const float num = rej ? (OSF - eP) : eP;
        const float den = rej ? (OSF - e0) : e0;
        prod *= num * rcp_fast(den);
    }

    // ---- Phase 4: block product reduction ----
    #pragma unroll
    for (int off = 16; off; off >>= 1)
        prod *= __shfl_xor_sync(0xffffffffu, prod, off);
    if (lane == 0) sRed[w] = prod;
    __syncthreads();
    if (tid < 32) {
        float pr = (tid < 8) ? sRed[tid] : 1.0f;
        #pragma unroll
        for (int off = 4; off; off >>= 1)
            pr *= __shfl_xor_sync(0xffffffffu, pr, off);
        if (tid == 0) out[b] = pr;
    }
}

extern "C" void kernel_launch(void* const* d_in, const int* in_sizes, int n_in,
                              void* d_out, int out_size) {
    const float4* Z4     = (const float4*)d_in[0];
    const float*  MT     = (const float*)d_in[1];
    const int*    OBS    = (const int*)d_in[2];   // int32 on device
    const float*  p_a    = (const float*)d_in[3];
    const float*  p_b    = (const float*)d_in[4];
    const float*  p_base = (const float*)d_in[5];
    float* out = (float*)d_out;

    const int B = out_size;   // 8192
    lund_weight_kernel<<<B, 256>>>(Z4, MT, OBS, p_a, p_b, p_base, out);
}

// round 11
// speedup vs baseline: 1.1746x; 1.1145x over previous
#include <cuda_runtime.h>
#include <math.h>

// LundWeight reweighting, round 11: R8 block-compaction skeleton with a
// minimum-issue scan: 4 warp-uniform groups of 32 quads, predicated count
// (2 slots/elem), one atomic per active group, fused predicated store that
// walks a byte address (3 slots/elem, no per-element IMAD).
// z (8192,128,25) f32; mT (8192,128) f32; observable (8192,2) i32 (mult=[:,0]).
// Output (8192,) f32.

#define LOG2E 1.4426950408889634f
#define F2MIN (-72.13475f)  /* -50 * LOG2E */
#define OSF   15.0f

__device__ __forceinline__ float rcp_fast(float x){ float r; asm("rcp.approx.f32 %0,%1;":"=f"(r):"f"(x)); return r; }
__device__ __forceinline__ float lg2_fast(float x){ float r; asm("lg2.approx.f32 %0,%1;":"=f"(r):"f"(x)); return r; }
__device__ __forceinline__ float ex2_fast(float x){ float r; asm("ex2.approx.f32 %0,%1;":"=f"(r):"f"(x)); return r; }

__device__ __forceinline__ float zmax_calc(float a, float b) {
    const float c = 1.0f;
    if (a < 0.02f) return (c > b) ? b : 1.0f;
    if (fabsf(a - c) < 0.01f) return b / (b + c);
    float z = 0.5f * (b + c - sqrtf((b - c) * (b - c) + 4.0f * a * b)) / (c - a);
    if (z > 0.9999f && b > 100.0f) z = fminf(z, 1.0f - a / b);
    return z;
}

// count += (z != 0): setp + predicated add = 2 issue slots.
__device__ __forceinline__ void cnt_step(int& c, float z) {
    asm("{ .reg .pred p; setp.ne.f32 p, %1, 0F00000000;\n\t"
        "  @p add.s32 %0, %0, 1; }\n" : "+r"(c) : "f"(z));
}

// if (z != 0) { store {z, idx} at byte addr ap; ap += 8; }  (3 issue slots)
__device__ __forceinline__ void sts_step(unsigned& ap, float z, int idx) {
    asm volatile(
        "{ .reg .pred p; setp.ne.f32 p, %1, 0F00000000;\n\t"
        "  @p st.shared.v2.f32 [%0], {%1, %2};\n\t"
        "  @p add.u32 %0, %0, 8; }\n"
        : "+r"(ap) : "f"(z), "f"(__int_as_float(idx)) : "memory");
}

__global__ __launch_bounds__(256) void lund_weight_kernel(
    const float4* __restrict__ Z4,     // (B,800) float4 view of (B,128,25)
    const float*  __restrict__ MT,     // (B,128)
    const int*    __restrict__ OBS,    // (B,2) int32, [:,0] = mult
    const float*  __restrict__ p_a,
    const float*  __restrict__ p_b,
    const float*  __restrict__ p_base,
    float* __restrict__ out)           // (B,)
{
    __shared__ float4 sK[128];      // {be2P, C2P, be20, C20} per m (log2 domain)
    __shared__ float2 sZM[3200];    // block-compacted {z, idx bits}
    __shared__ int    sCnt;
    __shared__ float  sRed[8];

    const int b    = blockIdx.x;
    const int tid  = threadIdx.x;
    const int w    = tid >> 5;
    const int lane = tid & 31;
    if (tid == 0) sCnt = 0;

    const float aP = p_a[0],    bP = p_b[0];
    const float a0 = p_base[0], b0 = p_base[1];
    const float aUP = (aP < 0.02f) ? 0.0f : aP;
    const float aU0 = (a0 < 0.02f) ? 0.0f : a0;

    const int mult = OBS[b * 2];             // 20..128

    // ---- Phase 1: 2 param-sets x 128 m; log2-domain constants:
    //      f2 = C2 - be2/z - lg2 z + aU*lg2(1-z);  be2 = b_exp*LOG2E;
    //      C2 = be2/zmax + lg2 zmax - aU*lg2(1-zmax).
    {
        const int   set  = tid >> 7;
        const int   m    = tid & 127;
        const float a    = set ? a0  : aP;
        const float bpar = set ? b0  : bP;
        const float aU   = set ? aU0 : aUP;
        const float mt   = MT[b * 128 + m];
        const float be   = bpar * mt * mt;
        const float zm   = zmax_calc(a, be);
        const float be2  = be * LOG2E;
        float C2 = be2 * rcp_fast(zm) + lg2_fast(zm);
        if (aU != 0.0f) C2 -= aU * lg2_fast(1.0f - zm);
        float* sKf = (float*)sK;
        sKf[(m << 2) + (set << 1) + 0] = be2;
        sKf[(m << 2) + (set << 1) + 1] = C2;
    }
    __syncthreads();   // sK + sCnt ready

    // ---- Phase 2: minimum-issue compaction of the valid region (first
    //      mult*25 floats; beyond that the row is exactly zero, quad-granular
    //      over-read is inert). 4 groups of 32 quads per warp, each group
    //      skipped warp-uniformly when past the valid region. ----
    const float4* __restrict__ zr = Z4 + (size_t)b * 800;
    const int nq = (mult * 25 + 3) >> 2;     // quads in valid region (<= 800)
    const unsigned sZMb = (unsigned)__cvta_generic_to_shared(sZM);

    #pragma unroll
    for (int k = 0; k < 4; ++k) {
        const int gw = (w << 5) + (k << 8);  // warp's first quad in group k
        if (gw < nq) {                       // warp-uniform guard
            const int g = gw + lane;
            float4 v = make_float4(0.f, 0.f, 0.f, 0.f);
            if (g < nq) v = zr[g];           // coalesced LDG.128

            int c = 0;
            cnt_step(c, v.x); cnt_step(c, v.y);
            cnt_step(c, v.z); cnt_step(c, v.w);

            unsigned ap = sZMb + 8u * (unsigned)atomicAdd(&sCnt, c);
            const int i0 = g << 2;
            sts_step(ap, v.x, i0 + 0);
            sts_step(ap, v.y, i0 + 1);
            sts_step(ap, v.z, i0 + 2);
            sts_step(ap, v.w, i0 + 3);
        }
    }
    __syncthreads();
    const int n = sCnt;

    // ---- Phase 3: dense math over active elements (identical to R8) ----
    float prod = 1.0f;
    #pragma unroll 1
    for (int i = tid; i < n; i += 256) {
        const float2 p   = sZM[i];
        const int    idx = __float_as_int(p.y);
        const int    m   = (idx * 5243) >> 17;   // exact idx/25 for idx<3200
        const bool   rej = (idx - m * 25) != 0;
        const float4 kk  = sK[m];
        const float  z   = p.x;

        const float rz  = rcp_fast(z);
        const float l2z = lg2_fast(z);
        const float l2o = lg2_fast(1.0f - z);

        float fP = fmaf(-kk.x, rz, kk.y);
        fP = fmaf(aUP, l2o, fP - l2z);
        float f0 = fmaf(-kk.z, rz, kk.w);
        f0 = fmaf(aU0, l2o, f0 - l2z);
        fP = fmaxf(fP, F2MIN);                // f <= 0 by construction
        f0 = fmaxf(f0, F2MIN);
        const float eP = ex2_fast(fP);
        const float e0 = ex2_fast(f0);

        const float num = rej ? (OSF - eP) : eP;
        const float den = rej ? (OSF - e0) : e0;
        prod *= num * rcp_fast(den);
    }

    // ---- Phase 4: block product reduction ----
    #pragma unroll
    for (int off = 16; off; off >>= 1)
        prod *= __shfl_xor_sync(0xffffffffu, prod, off);
    if (lane == 0) sRed[w] = prod;
    __syncthreads();
    if (tid < 32) {
        float pr = (tid < 8) ? sRed[tid] : 1.0f;
        #pragma unroll
        for (int off = 4; off; off >>= 1)
            pr *= __shfl_xor_sync(0xffffffffu, pr, off);
        if (tid == 0) out[b] = pr;
    }
}

extern "C" void kernel_launch(void* const* d_in, const int* in_sizes, int n_in,
                              void* d_out, int out_size) {
    const float4* Z4     = (const float4*)d_in[0];
    const float*  MT     = (const float*)d_in[1];
    const int*    OBS    = (const int*)d_in[2];   // int32 on device
    const float*  p_a    = (const float*)d_in[3];
    const float*  p_b    = (const float*)d_in[4];
    const float*  p_base = (const float*)d_in[5];
    float* out = (float*)d_out;

    const int B = out_size;   // 8192
    lund_weight_kernel<<<B, 256>>>(Z4, MT, OBS, p_a, p_b, p_base, out);
}